// round 16
// baseline (speedup 1.0000x reference)
#include <cuda_runtime.h>

#define NBATCH 1024
#define NV     6890
#define NJ     24
#define NBETA  10
#define NPOSE  207
#define NK     19
#define V3     20670          // NV*3
#define V3P    20736          // padded to 81*256 (16B-aligned rows)
#define KTOT   218            // 207 pose_feature + 10 shape + 1 (v_template)
#define NVP    6892           // NV padded to /4 (jrT rows)
#define NVL    6912           // NV padded to /128 (lwT rows)

__constant__ int c_parents[NJ] = {0,0,0,0,1,2,3,4,5,6,7,8,9,9,9,12,13,14,16,17,18,19,20,21};

// Scratch (device globals; no allocation allowed)
__device__ float g_coef[NBATCH * KTOT];      // per-batch blend coefficients
__device__ float g_A[NBATCH * NJ * 12];      // per-batch relative transforms, 3x4 rows
__device__ float g_Mjt[NJ * 11 * 3];         // [k][nb(10) | v_template(1)][xyz]
__device__ float g_jrT[NK * NVP];            // transposed, padded joint_regressor
__device__ float g_lwT[NJ * NVL];            // transposed, padded lbs_weights
__device__ float g_vposed[(size_t)NBATCH * V3];            // v_posed scratch (85 MB)
__device__ unsigned long long g_coefT2[KTOT * NBATCH];     // coef transposed+duplicated
__device__ float g_dirs[(size_t)KTOT * V3P];               // packed+padded dirs (18 MB)

// ---- packed fp32x2 helpers ----
#define FFMA2(d, a, b) asm("fma.rn.f32x2 %0, %1, %2, %0;" : "+l"(d) : "l"(a), "l"(b))
#define PACK2(d, s)    asm("mov.b64 %0, {%1, %1};" : "=l"(d) : "f"(s))
#define UNPACK2(lo, hi, s) asm("mov.b64 {%0, %1}, %2;" : "=f"(lo), "=f"(hi) : "l"(s))

// ---- cp.async helpers ----
__device__ __forceinline__ unsigned smem_u32(const void* p) {
    unsigned a;
    asm("{ .reg .u64 t; cvta.to.shared.u64 t, %1; cvt.u32.u64 %0, t; }" : "=r"(a) : "l"(p));
    return a;
}
#define CP_ASYNC16(dst, src) asm volatile("cp.async.ca.shared.global [%0], [%1], 16;" :: "r"(dst), "l"(src))
#define CP_COMMIT()          asm volatile("cp.async.commit_group;")
#define CP_WAIT(n)           asm volatile("cp.async.wait_group %0;" :: "n"(n))

// ---------------------------------------------------------------------------
// PREP: one kernel, four jobs by blockIdx range:
//   [0, 264):            Mjt reduction (k = b%24, col = b/24)
//   [264, 776):          jrT transpose (NK*NVP elems)
//   [776, 1423):         lwT transpose (NJ*NVL elems)
//   [1423, 1423+8829):   dirs pack (KTOT * V3P/2 float2s)
// ---------------------------------------------------------------------------
#define PREP_MJT   264
#define PREP_JRT   (PREP_MJT + (NK * NVP + 255) / 256)           // +512
#define PREP_LWT   (PREP_JRT + (NJ * NVL + 255) / 256)           // +648
#define PREP_DIRS  (PREP_LWT + (KTOT * (V3P / 2) + 255) / 256)   // +8829
// totals: 264, 776, 1424, 10253

__global__ __launch_bounds__(256) void prep(
    const float* __restrict__ reg,        // [V, 24]  smpl_j_regressor
    const float* __restrict__ shapedirs,  // [10, V3]
    const float* __restrict__ v_template, // [V3]
    const float* __restrict__ posedirs,   // [207, V3]
    const float* __restrict__ jr,         // [V, 19]
    const float* __restrict__ lbsw)       // [V, 24]
{
    int blk = blockIdx.x;
    int tid = threadIdx.x;

    if (blk < PREP_MJT) {
        int k = blk % NJ, col = blk / NJ;
        const float* X = (col < NBETA) ? (shapedirs + (size_t)col * V3) : v_template;
        float a0 = 0.f, a1 = 0.f, a2 = 0.f;
        for (int v = tid; v < NV; v += 256) {
            float r = reg[v * NJ + k];
            a0 += r * X[v * 3 + 0];
            a1 += r * X[v * 3 + 1];
            a2 += r * X[v * 3 + 2];
        }
        __shared__ float s_part[8][3];
        #pragma unroll
        for (int off = 16; off; off >>= 1) {
            a0 += __shfl_down_sync(0xffffffffu, a0, off);
            a1 += __shfl_down_sync(0xffffffffu, a1, off);
            a2 += __shfl_down_sync(0xffffffffu, a2, off);
        }
        int lane = tid & 31, w = tid >> 5;
        if (lane == 0) { s_part[w][0] = a0; s_part[w][1] = a1; s_part[w][2] = a2; }
        __syncthreads();
        if (tid == 0) {
            float r0 = 0.f, r1 = 0.f, r2 = 0.f;
            #pragma unroll
            for (int i = 0; i < 8; i++) { r0 += s_part[i][0]; r1 += s_part[i][1]; r2 += s_part[i][2]; }
            g_Mjt[(k * 11 + col) * 3 + 0] = r0;
            g_Mjt[(k * 11 + col) * 3 + 1] = r1;
            g_Mjt[(k * 11 + col) * 3 + 2] = r2;
        }
    } else if (blk < PREP_JRT) {
        int idx = (blk - PREP_MJT) * 256 + tid;
        if (idx < NK * NVP) {
            int k = idx / NVP, v = idx - k * NVP;
            g_jrT[idx] = (v < NV) ? jr[v * NK + k] : 0.f;
        }
    } else if (blk < PREP_LWT) {
        int idx = (blk - PREP_JRT) * 256 + tid;
        if (idx < NJ * NVL) {
            int j = idx / NVL, v = idx - j * NVL;
            g_lwT[idx] = (v < NV) ? lbsw[(size_t)v * NJ + j] : 0.f;
        }
    } else {
        int i = (blk - PREP_LWT) * 256 + tid;       // float2 index
        const int HALF = V3P / 2;                   // 10368
        if (i < KTOT * HALF) {
            int k = i / HALF, c2 = i - k * HALF;
            int col = c2 * 2;
            float2 val = make_float2(0.f, 0.f);
            if (col < V3) {
                const float* src;
                if (k < NPOSE)      src = posedirs + (size_t)k * V3;
                else if (k < 217)   src = shapedirs + (size_t)(k - NPOSE) * V3;
                else                src = v_template;
                val = *(const float2*)(src + col);
            }
            *(float2*)&g_dirs[(size_t)k * V3P + col] = val;
        }
    }
}

// ---------------------------------------------------------------------------
// K1: per-batch Rodrigues, coef vector (+ packed transposed copy), joints,
// kinematic chain, rel A.
// ---------------------------------------------------------------------------
__device__ __forceinline__ void coef_store(int b, int k, float v) {
    g_coef[(size_t)b * KTOT + k] = v;
    unsigned long long dv; PACK2(dv, v);
    g_coefT2[k * NBATCH + b] = dv;
}

__global__ __launch_bounds__(64) void k1_batch(
    const float* __restrict__ in,     // [B, 82]
    float* __restrict__ out_Rs)       // [B, 24, 3, 3]
{
    int b = blockIdx.x, tid = threadIdx.x;
    __shared__ float s_R[NJ][9];
    __shared__ float s_Js[NJ][3];
    __shared__ float s_G[NJ][12];
    const float* pin = in + (size_t)b * 82;

    if (tid < NJ) {
        float ax = pin[tid * 3 + 0], ay = pin[tid * 3 + 1], az = pin[tid * 3 + 2];
        float ang = sqrtf(ax * ax + ay * ay + az * az + 1e-8f);
        float x = ax / ang, y = ay / ang, z = az / ang;
        float cth = cosf(ang), sth = sinf(ang), C = 1.f - cth;
        float R[9];
        R[0] = cth + C * x * x;  R[1] = C * x * y - sth * z; R[2] = C * x * z + sth * y;
        R[3] = C * x * y + sth * z; R[4] = cth + C * y * y;  R[5] = C * y * z - sth * x;
        R[6] = C * x * z - sth * y; R[7] = C * y * z + sth * x; R[8] = cth + C * z * z;
        #pragma unroll
        for (int i = 0; i < 9; i++) {
            s_R[tid][i] = R[i];
            out_Rs[(size_t)b * 216 + tid * 9 + i] = R[i];
        }
        if (tid >= 1) {
            #pragma unroll
            for (int i = 0; i < 9; i++)
                coef_store(b, (tid - 1) * 9 + i,
                           R[i] - ((i == 0 || i == 4 || i == 8) ? 1.f : 0.f));
        }
        #pragma unroll
        for (int c = 0; c < 3; c++) {
            float val = g_Mjt[(tid * 11 + 10) * 3 + c];
            #pragma unroll
            for (int nb = 0; nb < NBETA; nb++)
                val += pin[72 + nb] * g_Mjt[(tid * 11 + nb) * 3 + c];
            s_Js[tid][c] = val;
        }
    } else if (tid < NJ + NBETA) {
        coef_store(b, NPOSE + (tid - NJ), pin[72 + (tid - NJ)]);
    } else if (tid == NJ + NBETA) {
        coef_store(b, 217, 1.f);
    }
    __syncthreads();

    if (tid == 0) {
        #pragma unroll
        for (int r = 0; r < 3; r++) {
            s_G[0][r * 4 + 0] = s_R[0][r * 3 + 0];
            s_G[0][r * 4 + 1] = s_R[0][r * 3 + 1];
            s_G[0][r * 4 + 2] = s_R[0][r * 3 + 2];
            s_G[0][r * 4 + 3] = s_Js[0][r];
        }
        for (int j = 1; j < NJ; j++) {
            int p = c_parents[j];
            float tx = s_Js[j][0] - s_Js[p][0];
            float ty = s_Js[j][1] - s_Js[p][1];
            float tz = s_Js[j][2] - s_Js[p][2];
            #pragma unroll
            for (int r = 0; r < 3; r++) {
                float g0 = s_G[p][r * 4 + 0], g1 = s_G[p][r * 4 + 1];
                float g2 = s_G[p][r * 4 + 2], gt = s_G[p][r * 4 + 3];
                s_G[j][r * 4 + 0] = g0 * s_R[j][0] + g1 * s_R[j][3] + g2 * s_R[j][6];
                s_G[j][r * 4 + 1] = g0 * s_R[j][1] + g1 * s_R[j][4] + g2 * s_R[j][7];
                s_G[j][r * 4 + 2] = g0 * s_R[j][2] + g1 * s_R[j][5] + g2 * s_R[j][8];
                s_G[j][r * 4 + 3] = g0 * tx + g1 * ty + g2 * tz + gt;
            }
        }
    }
    __syncthreads();

    if (tid < NJ) {
        int j = tid;
        #pragma unroll
        for (int r = 0; r < 3; r++) {
            float g0 = s_G[j][r * 4 + 0], g1 = s_G[j][r * 4 + 1], g2 = s_G[j][r * 4 + 2];
            float t = s_G[j][r * 4 + 3] - (g0 * s_Js[j][0] + g1 * s_Js[j][1] + g2 * s_Js[j][2]);
            size_t o = (size_t)b * 288 + j * 12 + r * 4;
            g_A[o + 0] = g0; g_A[o + 1] = g1; g_A[o + 2] = g2; g_A[o + 3] = t;
        }
    }
}

// ---------------------------------------------------------------------------
// K2a: blendshape GEMM -> g_vposed, double-buffered cp.async SGEMM.
//   Block = 64 batches x 256 cols, 256 threads. Thread tile 8b x 8c. KTA=16.
// smem: s_coef2 ull[2][16 k][8 g][10] @0 (20480B), s_dirs f32[2][16][256] @20480 (32768B)
// ---------------------------------------------------------------------------
#define TCA   256
#define KTA   16
#define SMEM_K2A 53248
#define NTILES ((KTOT + KTA - 1) / KTA)   // 14

__global__ __launch_bounds__(256, 2) void k2a_gemm()
{
    extern __shared__ char smem[];
    const unsigned long long* s_coef2 = (const unsigned long long*)smem; // [2][16][8][10]
    const float* s_dirs = (const float*)(smem + 20480);                  // [2][16][256]
    unsigned smem_base = smem_u32(smem);

    int tid = threadIdx.x;
    int cbase = blockIdx.x * TCA;
    int bbase = blockIdx.y * 64;

    int lane = tid & 31;
    int wid  = tid >> 5;
    int g    = lane >> 2;               // batch group (8 batches)
    int cg2  = lane & 3;                // col group within warp slice
    int bq   = g * 8;                   // first batch of group
    int c0   = wid * 32 + cg2 * 8;      // first col of thread tile

#define STAGE(T, BUF)                                                          \
    {                                                                          \
        int kt_ = (T) * KTA;                                                   \
        int kmax_ = min(KTA, KTOT - kt_);                                      \
        for (int i = tid; i < kmax_ * 32; i += 256) {                          \
            int r = i >> 5, cc = i & 31;                                       \
            int gg = cc >> 2;                                                  \
            unsigned dst = smem_base + (BUF) * 10240 + r * 640 + cc * 16 + gg * 16; \
            const char* src = (const char*)&g_coefT2[(kt_ + r) * NBATCH + bbase] + cc * 16; \
            CP_ASYNC16(dst, src);                                              \
        }                                                                      \
        for (int i = tid; i < kmax_ * 64; i += 256) {                          \
            int r = i >> 6, ci = i & 63;                                       \
            unsigned dst = smem_base + 20480 + (BUF) * 16384 + r * 1024 + ci * 16;\
            const float* src = g_dirs + (size_t)(kt_ + r) * V3P + cbase + ci * 4; \
            CP_ASYNC16(dst, src);                                              \
        }                                                                      \
        CP_COMMIT();                                                           \
    }

    unsigned long long acc[8][4];
    #pragma unroll
    for (int i = 0; i < 8; i++)
        #pragma unroll
        for (int p = 0; p < 4; p++) acc[i][p] = 0ull;

#define GEMM_STEP(BUF, KK)                                                     \
    {                                                                          \
        const unsigned long long* cf = s_coef2 + (BUF) * 1280 + (KK) * 80 + g * 10; \
        ulonglong2 q0 = *(const ulonglong2*)(cf + 0);                          \
        ulonglong2 q1 = *(const ulonglong2*)(cf + 2);                          \
        ulonglong2 q2 = *(const ulonglong2*)(cf + 4);                          \
        ulonglong2 q3 = *(const ulonglong2*)(cf + 6);                          \
        const float* dr = s_dirs + (BUF) * 4096 + (KK) * 256 + c0;             \
        ulonglong2 d01 = *(const ulonglong2*)(dr);                             \
        ulonglong2 d23 = *(const ulonglong2*)(dr + 4);                         \
        FFMA2(acc[0][0], q0.x, d01.x); FFMA2(acc[0][1], q0.x, d01.y);          \
        FFMA2(acc[0][2], q0.x, d23.x); FFMA2(acc[0][3], q0.x, d23.y);          \
        FFMA2(acc[1][0], q0.y, d01.x); FFMA2(acc[1][1], q0.y, d01.y);          \
        FFMA2(acc[1][2], q0.y, d23.x); FFMA2(acc[1][3], q0.y, d23.y);          \
        FFMA2(acc[2][0], q1.x, d01.x); FFMA2(acc[2][1], q1.x, d01.y);          \
        FFMA2(acc[2][2], q1.x, d23.x); FFMA2(acc[2][3], q1.x, d23.y);          \
        FFMA2(acc[3][0], q1.y, d01.x); FFMA2(acc[3][1], q1.y, d01.y);          \
        FFMA2(acc[3][2], q1.y, d23.x); FFMA2(acc[3][3], q1.y, d23.y);          \
        FFMA2(acc[4][0], q2.x, d01.x); FFMA2(acc[4][1], q2.x, d01.y);          \
        FFMA2(acc[4][2], q2.x, d23.x); FFMA2(acc[4][3], q2.x, d23.y);          \
        FFMA2(acc[5][0], q2.y, d01.x); FFMA2(acc[5][1], q2.y, d01.y);          \
        FFMA2(acc[5][2], q2.y, d23.x); FFMA2(acc[5][3], q2.y, d23.y);          \
        FFMA2(acc[6][0], q3.x, d01.x); FFMA2(acc[6][1], q3.x, d01.y);          \
        FFMA2(acc[6][2], q3.x, d23.x); FFMA2(acc[6][3], q3.x, d23.y);          \
        FFMA2(acc[7][0], q3.y, d01.x); FFMA2(acc[7][1], q3.y, d01.y);          \
        FFMA2(acc[7][2], q3.y, d23.x); FFMA2(acc[7][3], q3.y, d23.y);          \
    }

    STAGE(0, 0)
    for (int t = 0; t < NTILES; t++) {
        int buf = t & 1;
        if (t + 1 < NTILES) {
            STAGE(t + 1, buf ^ 1)
            CP_WAIT(1);
        } else {
            CP_WAIT(0);
        }
        __syncthreads();
        int kmax = min(KTA, KTOT - t * KTA);
        if (kmax == KTA) {
            if (buf == 0) {
                #pragma unroll
                for (int kk = 0; kk < KTA; kk++) GEMM_STEP(0, kk)
            } else {
                #pragma unroll
                for (int kk = 0; kk < KTA; kk++) GEMM_STEP(1, kk)
            }
        } else {
            for (int kk = 0; kk < kmax; kk++) GEMM_STEP(buf, kk)
        }
        __syncthreads();
    }
#undef GEMM_STEP
#undef STAGE

    #pragma unroll
    for (int bi = 0; bi < 8; bi++) {
        size_t row = (size_t)(bbase + bq + bi) * V3;
        #pragma unroll
        for (int p = 0; p < 4; p++) {
            int col = cbase + c0 + p * 2;
            if (col < V3)
                *(unsigned long long*)&g_vposed[row + col] = acc[bi][p];
        }
    }
}

// ---------------------------------------------------------------------------
// K2b: LBS skinning. Block = 16 batches x 128 verts, 256 threads.
//   WT staging now coalesced float4 from pre-transposed g_lwT.
//   Dynamic smem (49792 B): s_A2 ull[16][290] @0, s_WT f32[24][132] @37120.
// ---------------------------------------------------------------------------
#define SMEM_K2B 49792

__global__ __launch_bounds__(256) void k2b_lbs(
    float* __restrict__ out_verts)        // [B, V, 3]
{
    extern __shared__ char smemb[];
    unsigned long long* s_A2 = (unsigned long long*)smemb;   // [16][290]
    float* s_WT = (float*)(smemb + 37120);                   // [24][132]

    int tid = threadIdx.x;
    int vbase = blockIdx.x * 128;
    int bbase = blockIdx.y * 16;

    for (int i = tid; i < 16 * 288; i += 256) {
        int b = i / 288, j = i - b * 288;
        float v = g_A[(size_t)(bbase + b) * 288 + j];
        unsigned long long dv; PACK2(dv, v);
        s_A2[b * 290 + j] = dv;
    }
    for (int i = tid; i < 24 * 32; i += 256) {
        int j = i >> 5, q = i & 31;
        float4 w = *(const float4*)&g_lwT[j * NVL + vbase + q * 4];
        *(float4*)&s_WT[j * 132 + q * 4] = w;
    }
    __syncthreads();

    int bg = tid >> 4;        // 0..15 batch
    int vg = tid & 15;        // vertex group
    size_t brow = (size_t)(bbase + bg) * V3;

    #pragma unroll
    for (int pass = 0; pass < 2; pass++) {
        int v0 = vg * 4 + pass * 64;

        unsigned long long T[24];
        #pragma unroll
        for (int i = 0; i < 24; i++) T[i] = 0ull;

        #pragma unroll 4
        for (int j = 0; j < NJ; j++) {
            ulonglong2 W = *(const ulonglong2*)&s_WT[j * 132 + v0];
            const unsigned long long* Ab = &s_A2[bg * 290 + j * 12];
            ulonglong2 a0 = *(const ulonglong2*)(Ab + 0);
            ulonglong2 a1 = *(const ulonglong2*)(Ab + 2);
            ulonglong2 a2 = *(const ulonglong2*)(Ab + 4);
            ulonglong2 a3 = *(const ulonglong2*)(Ab + 6);
            ulonglong2 a4 = *(const ulonglong2*)(Ab + 8);
            ulonglong2 a5 = *(const ulonglong2*)(Ab + 10);
            FFMA2(T[0],  W.x, a0.x); FFMA2(T[1],  W.x, a0.y);
            FFMA2(T[2],  W.x, a1.x); FFMA2(T[3],  W.x, a1.y);
            FFMA2(T[4],  W.x, a2.x); FFMA2(T[5],  W.x, a2.y);
            FFMA2(T[6],  W.x, a3.x); FFMA2(T[7],  W.x, a3.y);
            FFMA2(T[8],  W.x, a4.x); FFMA2(T[9],  W.x, a4.y);
            FFMA2(T[10], W.x, a5.x); FFMA2(T[11], W.x, a5.y);
            FFMA2(T[12], W.y, a0.x); FFMA2(T[13], W.y, a0.y);
            FFMA2(T[14], W.y, a1.x); FFMA2(T[15], W.y, a1.y);
            FFMA2(T[16], W.y, a2.x); FFMA2(T[17], W.y, a2.y);
            FFMA2(T[18], W.y, a3.x); FFMA2(T[19], W.y, a3.y);
            FFMA2(T[20], W.y, a4.x); FFMA2(T[21], W.y, a4.y);
            FFMA2(T[22], W.y, a5.x); FFMA2(T[23], W.y, a5.y);
        }

        #pragma unroll
        for (int vp = 0; vp < 2; vp++) {
            float flo[12], fhi[12];
            #pragma unroll
            for (int c = 0; c < 12; c++) UNPACK2(flo[c], fhi[c], T[vp * 12 + c]);
            {
                int gv = vbase + v0 + vp * 2;
                if (gv < NV) {
                    const float* pp = g_vposed + brow + gv * 3;
                    float x = pp[0], y = pp[1], z = pp[2];
                    float* oo = out_verts + brow + gv * 3;
                    oo[0] = fmaf(flo[0], x, fmaf(flo[1], y, fmaf(flo[2],  z, flo[3])));
                    oo[1] = fmaf(flo[4], x, fmaf(flo[5], y, fmaf(flo[6],  z, flo[7])));
                    oo[2] = fmaf(flo[8], x, fmaf(flo[9], y, fmaf(flo[10], z, flo[11])));
                }
            }
            {
                int gv = vbase + v0 + vp * 2 + 1;
                if (gv < NV) {
                    const float* pp = g_vposed + brow + gv * 3;
                    float x = pp[0], y = pp[1], z = pp[2];
                    float* oo = out_verts + brow + gv * 3;
                    oo[0] = fmaf(fhi[0], x, fmaf(fhi[1], y, fmaf(fhi[2],  z, fhi[3])));
                    oo[1] = fmaf(fhi[4], x, fmaf(fhi[5], y, fmaf(fhi[6],  z, fhi[7])));
                    oo[2] = fmaf(fhi[8], x, fmaf(fhi[9], y, fmaf(fhi[10], z, fhi[11])));
                }
            }
        }
    }
}

// ---------------------------------------------------------------------------
// K3: joints[b,k,c] = sum_v jrT[k][v] * verts[b,v,c]; 2 batches per block.
// ---------------------------------------------------------------------------
__global__ __launch_bounds__(256) void k3_joints(
    const float* __restrict__ verts,    // [B, V, 3]
    float* __restrict__ out_joints)     // [B, 19, 3]
{
    int b0 = blockIdx.x * 2, tid = threadIdx.x;
    const float* vb0 = verts + (size_t)b0 * V3;
    const float* vb1 = vb0 + V3;
    float acc0[NK * 3], acc1[NK * 3];
    #pragma unroll
    for (int i = 0; i < NK * 3; i++) { acc0[i] = 0.f; acc1[i] = 0.f; }

    const int NQ = (NV + 3) / 4;
    for (int q = tid; q < NQ; q += 256) {
        int v0 = q * 4;
        const float* p0 = vb0 + v0 * 3;
        const float* p1 = vb1 + v0 * 3;
        float2 a0 = *(const float2*)(p0 + 0), a1 = *(const float2*)(p0 + 2);
        float2 a2 = *(const float2*)(p0 + 4), a3 = *(const float2*)(p0 + 6);
        float2 a4 = *(const float2*)(p0 + 8), a5 = *(const float2*)(p0 + 10);
        float2 c0 = *(const float2*)(p1 + 0), c1 = *(const float2*)(p1 + 2);
        float2 c2 = *(const float2*)(p1 + 4), c3 = *(const float2*)(p1 + 6);
        float2 c4 = *(const float2*)(p1 + 8), c5 = *(const float2*)(p1 + 10);
        #pragma unroll
        for (int k = 0; k < NK; k++) {
            float4 w = *(const float4*)&g_jrT[k * NVP + v0];
            acc0[k * 3 + 0] += w.x * a0.x + w.y * a1.y + w.z * a3.x + w.w * a4.y;
            acc0[k * 3 + 1] += w.x * a0.y + w.y * a2.x + w.z * a3.y + w.w * a5.x;
            acc0[k * 3 + 2] += w.x * a1.x + w.y * a2.y + w.z * a4.x + w.w * a5.y;
            acc1[k * 3 + 0] += w.x * c0.x + w.y * c1.y + w.z * c3.x + w.w * c4.y;
            acc1[k * 3 + 1] += w.x * c0.y + w.y * c2.x + w.z * c3.y + w.w * c5.x;
            acc1[k * 3 + 2] += w.x * c1.x + w.y * c2.y + w.z * c4.x + w.w * c5.y;
        }
    }

    __shared__ float s_part[8][2 * 58];
    int lane = tid & 31, wp = tid >> 5;
    #pragma unroll
    for (int i = 0; i < NK * 3; i++) {
        float v0 = acc0[i], v1 = acc1[i];
        #pragma unroll
        for (int off = 16; off; off >>= 1) {
            v0 += __shfl_down_sync(0xffffffffu, v0, off);
            v1 += __shfl_down_sync(0xffffffffu, v1, off);
        }
        if (lane == 0) { s_part[wp][i] = v0; s_part[wp][58 + i] = v1; }
    }
    __syncthreads();
    if (tid < 2 * NK * 3) {
        int h = tid / (NK * 3), i = tid - h * (NK * 3);
        float s = 0.f;
        #pragma unroll
        for (int w = 0; w < 8; w++) s += s_part[w][h * 58 + i];
        out_joints[(size_t)(b0 + h) * (NK * 3) + i] = s;
    }
}

// ---------------------------------------------------------------------------
extern "C" void kernel_launch(void* const* d_in, const int* in_sizes, int n_in,
                              void* d_out, int out_size) {
    const float* inputs    = (const float*)d_in[0];  // [B, 82]
    const float* v_tmpl    = (const float*)d_in[1];  // [V, 3]
    const float* shapedirs = (const float*)d_in[2];  // [10, V3]
    const float* jreg      = (const float*)d_in[3];  // [V, 24]
    const float* posedirs  = (const float*)d_in[4];  // [207, V3]
    const float* lbsw      = (const float*)d_in[5];  // [V, 24]
    const float* jntreg    = (const float*)d_in[6];  // [V, 19]

    float* out        = (float*)d_out;
    float* out_verts  = out;                                   // B*V*3
    float* out_joints = out + (size_t)NBATCH * NV * 3;         // B*19*3
    float* out_Rs     = out_joints + (size_t)NBATCH * NK * 3;  // B*24*9

    cudaFuncSetAttribute(k2a_gemm, cudaFuncAttributeMaxDynamicSharedMemorySize, SMEM_K2A);
    cudaFuncSetAttribute(k2b_lbs, cudaFuncAttributeMaxDynamicSharedMemorySize, SMEM_K2B);

    prep<<<PREP_DIRS, 256>>>(jreg, shapedirs, v_tmpl, posedirs, jntreg, lbsw);
    k1_batch<<<NBATCH, 64>>>(inputs, out_Rs);
    k2a_gemm<<<dim3(V3P / TCA, NBATCH / 64), 256, SMEM_K2A>>>();
    k2b_lbs<<<dim3((NV + 127) / 128, NBATCH / 16), 256, SMEM_K2B>>>(out_verts);
    k3_joints<<<NBATCH / 2, 256>>>(out_verts, out_joints);
}

// round 17
// speedup vs baseline: 1.0737x; 1.0737x over previous
#include <cuda_runtime.h>

#define NBATCH 1024
#define NV     6890
#define NJ     24
#define NBETA  10
#define NPOSE  207
#define NK     19
#define V3     20670          // NV*3
#define V3P    20736          // padded to 81*256 (16B-aligned rows)
#define KTOT   218            // 207 pose_feature + 10 shape + 1 (v_template)
#define NVP    6892           // NV padded to /4 (jrT rows)
#define NVL    6912           // NV padded to /128 (lwT rows)

__constant__ int c_parents[NJ] = {0,0,0,0,1,2,3,4,5,6,7,8,9,9,9,12,13,14,16,17,18,19,20,21};

// Scratch (device globals; no allocation allowed)
__device__ float g_coef[NBATCH * KTOT];      // per-batch blend coefficients
__device__ float g_A[NBATCH * NJ * 12];      // per-batch relative transforms, 3x4 rows
__device__ float g_Mjt[NJ * 11 * 3];         // [k][nb(10) | v_template(1)][xyz]
__device__ float g_jrT[NK * NVP];            // transposed, padded joint_regressor
__device__ float g_lwT[NJ * NVL];            // transposed, padded lbs_weights
__device__ float g_vposed[(size_t)NBATCH * V3];            // v_posed scratch (85 MB)
__device__ unsigned long long g_coefT2[KTOT * NBATCH];     // coef transposed+duplicated
__device__ float g_dirs[(size_t)KTOT * V3P];               // packed+padded dirs (18 MB)

// ---- packed fp32x2 helpers ----
#define FFMA2(d, a, b) asm("fma.rn.f32x2 %0, %1, %2, %0;" : "+l"(d) : "l"(a), "l"(b))
#define PACK2(d, s)    asm("mov.b64 %0, {%1, %1};" : "=l"(d) : "f"(s))
#define UNPACK2(lo, hi, s) asm("mov.b64 {%0, %1}, %2;" : "=f"(lo), "=f"(hi) : "l"(s))

// ---- cp.async helpers ----
__device__ __forceinline__ unsigned smem_u32(const void* p) {
    unsigned a;
    asm("{ .reg .u64 t; cvta.to.shared.u64 t, %1; cvt.u32.u64 %0, t; }" : "=r"(a) : "l"(p));
    return a;
}
#define CP_ASYNC16(dst, src) asm volatile("cp.async.ca.shared.global [%0], [%1], 16;" :: "r"(dst), "l"(src))
#define CP_COMMIT()          asm volatile("cp.async.commit_group;")
#define CP_WAIT(n)           asm volatile("cp.async.wait_group %0;" :: "n"(n))

// ---------------------------------------------------------------------------
// PREP: one kernel, four jobs by blockIdx range.
// ---------------------------------------------------------------------------
#define PREP_MJT   264
#define PREP_JRT   (PREP_MJT + (NK * NVP + 255) / 256)
#define PREP_LWT   (PREP_JRT + (NJ * NVL + 255) / 256)
#define PREP_DIRS  (PREP_LWT + (KTOT * (V3P / 2) + 255) / 256)

__global__ __launch_bounds__(256) void prep(
    const float* __restrict__ reg,        // [V, 24]  smpl_j_regressor
    const float* __restrict__ shapedirs,  // [10, V3]
    const float* __restrict__ v_template, // [V3]
    const float* __restrict__ posedirs,   // [207, V3]
    const float* __restrict__ jr,         // [V, 19]
    const float* __restrict__ lbsw)       // [V, 24]
{
    int blk = blockIdx.x;
    int tid = threadIdx.x;

    if (blk < PREP_MJT) {
        int k = blk % NJ, col = blk / NJ;
        const float* X = (col < NBETA) ? (shapedirs + (size_t)col * V3) : v_template;
        float a0 = 0.f, a1 = 0.f, a2 = 0.f;
        for (int v = tid; v < NV; v += 256) {
            float r = reg[v * NJ + k];
            a0 += r * X[v * 3 + 0];
            a1 += r * X[v * 3 + 1];
            a2 += r * X[v * 3 + 2];
        }
        __shared__ float s_part[8][3];
        #pragma unroll
        for (int off = 16; off; off >>= 1) {
            a0 += __shfl_down_sync(0xffffffffu, a0, off);
            a1 += __shfl_down_sync(0xffffffffu, a1, off);
            a2 += __shfl_down_sync(0xffffffffu, a2, off);
        }
        int lane = tid & 31, w = tid >> 5;
        if (lane == 0) { s_part[w][0] = a0; s_part[w][1] = a1; s_part[w][2] = a2; }
        __syncthreads();
        if (tid == 0) {
            float r0 = 0.f, r1 = 0.f, r2 = 0.f;
            #pragma unroll
            for (int i = 0; i < 8; i++) { r0 += s_part[i][0]; r1 += s_part[i][1]; r2 += s_part[i][2]; }
            g_Mjt[(k * 11 + col) * 3 + 0] = r0;
            g_Mjt[(k * 11 + col) * 3 + 1] = r1;
            g_Mjt[(k * 11 + col) * 3 + 2] = r2;
        }
    } else if (blk < PREP_JRT) {
        int idx = (blk - PREP_MJT) * 256 + tid;
        if (idx < NK * NVP) {
            int k = idx / NVP, v = idx - k * NVP;
            g_jrT[idx] = (v < NV) ? jr[v * NK + k] : 0.f;
        }
    } else if (blk < PREP_LWT) {
        int idx = (blk - PREP_JRT) * 256 + tid;
        if (idx < NJ * NVL) {
            int j = idx / NVL, v = idx - j * NVL;
            g_lwT[idx] = (v < NV) ? lbsw[(size_t)v * NJ + j] : 0.f;
        }
    } else {
        int i = (blk - PREP_LWT) * 256 + tid;       // float2 index
        const int HALF = V3P / 2;                   // 10368
        if (i < KTOT * HALF) {
            int k = i / HALF, c2 = i - k * HALF;
            int col = c2 * 2;
            float2 val = make_float2(0.f, 0.f);
            if (col < V3) {
                const float* src;
                if (k < NPOSE)      src = posedirs + (size_t)k * V3;
                else if (k < 217)   src = shapedirs + (size_t)(k - NPOSE) * V3;
                else                src = v_template;
                val = *(const float2*)(src + col);
            }
            *(float2*)&g_dirs[(size_t)k * V3P + col] = val;
        }
    }
}

// ---------------------------------------------------------------------------
// K1: per-batch Rodrigues, coef vector (+ packed transposed copy), joints,
// kinematic chain, rel A.
// ---------------------------------------------------------------------------
__device__ __forceinline__ void coef_store(int b, int k, float v) {
    g_coef[(size_t)b * KTOT + k] = v;
    unsigned long long dv; PACK2(dv, v);
    g_coefT2[k * NBATCH + b] = dv;
}

__global__ __launch_bounds__(64) void k1_batch(
    const float* __restrict__ in,     // [B, 82]
    float* __restrict__ out_Rs)       // [B, 24, 3, 3]
{
    int b = blockIdx.x, tid = threadIdx.x;
    __shared__ float s_R[NJ][9];
    __shared__ float s_Js[NJ][3];
    __shared__ float s_G[NJ][12];
    const float* pin = in + (size_t)b * 82;

    if (tid < NJ) {
        float ax = pin[tid * 3 + 0], ay = pin[tid * 3 + 1], az = pin[tid * 3 + 2];
        float ang = sqrtf(ax * ax + ay * ay + az * az + 1e-8f);
        float x = ax / ang, y = ay / ang, z = az / ang;
        float cth = cosf(ang), sth = sinf(ang), C = 1.f - cth;
        float R[9];
        R[0] = cth + C * x * x;  R[1] = C * x * y - sth * z; R[2] = C * x * z + sth * y;
        R[3] = C * x * y + sth * z; R[4] = cth + C * y * y;  R[5] = C * y * z - sth * x;
        R[6] = C * x * z - sth * y; R[7] = C * y * z + sth * x; R[8] = cth + C * z * z;
        #pragma unroll
        for (int i = 0; i < 9; i++) {
            s_R[tid][i] = R[i];
            out_Rs[(size_t)b * 216 + tid * 9 + i] = R[i];
        }
        if (tid >= 1) {
            #pragma unroll
            for (int i = 0; i < 9; i++)
                coef_store(b, (tid - 1) * 9 + i,
                           R[i] - ((i == 0 || i == 4 || i == 8) ? 1.f : 0.f));
        }
        #pragma unroll
        for (int c = 0; c < 3; c++) {
            float val = g_Mjt[(tid * 11 + 10) * 3 + c];
            #pragma unroll
            for (int nb = 0; nb < NBETA; nb++)
                val += pin[72 + nb] * g_Mjt[(tid * 11 + nb) * 3 + c];
            s_Js[tid][c] = val;
        }
    } else if (tid < NJ + NBETA) {
        coef_store(b, NPOSE + (tid - NJ), pin[72 + (tid - NJ)]);
    } else if (tid == NJ + NBETA) {
        coef_store(b, 217, 1.f);
    }
    __syncthreads();

    if (tid == 0) {
        #pragma unroll
        for (int r = 0; r < 3; r++) {
            s_G[0][r * 4 + 0] = s_R[0][r * 3 + 0];
            s_G[0][r * 4 + 1] = s_R[0][r * 3 + 1];
            s_G[0][r * 4 + 2] = s_R[0][r * 3 + 2];
            s_G[0][r * 4 + 3] = s_Js[0][r];
        }
        for (int j = 1; j < NJ; j++) {
            int p = c_parents[j];
            float tx = s_Js[j][0] - s_Js[p][0];
            float ty = s_Js[j][1] - s_Js[p][1];
            float tz = s_Js[j][2] - s_Js[p][2];
            #pragma unroll
            for (int r = 0; r < 3; r++) {
                float g0 = s_G[p][r * 4 + 0], g1 = s_G[p][r * 4 + 1];
                float g2 = s_G[p][r * 4 + 2], gt = s_G[p][r * 4 + 3];
                s_G[j][r * 4 + 0] = g0 * s_R[j][0] + g1 * s_R[j][3] + g2 * s_R[j][6];
                s_G[j][r * 4 + 1] = g0 * s_R[j][1] + g1 * s_R[j][4] + g2 * s_R[j][7];
                s_G[j][r * 4 + 2] = g0 * s_R[j][2] + g1 * s_R[j][5] + g2 * s_R[j][8];
                s_G[j][r * 4 + 3] = g0 * tx + g1 * ty + g2 * tz + gt;
            }
        }
    }
    __syncthreads();

    if (tid < NJ) {
        int j = tid;
        #pragma unroll
        for (int r = 0; r < 3; r++) {
            float g0 = s_G[j][r * 4 + 0], g1 = s_G[j][r * 4 + 1], g2 = s_G[j][r * 4 + 2];
            float t = s_G[j][r * 4 + 3] - (g0 * s_Js[j][0] + g1 * s_Js[j][1] + g2 * s_Js[j][2]);
            size_t o = (size_t)b * 288 + j * 12 + r * 4;
            g_A[o + 0] = g0; g_A[o + 1] = g1; g_A[o + 2] = g2; g_A[o + 3] = t;
        }
    }
}

// ---------------------------------------------------------------------------
// K2a: blendshape GEMM -> g_vposed, double-buffered cp.async SGEMM.
//   Block = 64 batches x 256 cols, 256 threads. Thread tile 8b x 8c. KTA=16.
// smem: s_coef2 ull[2][16 k][8 g][10] @0 (20480B), s_dirs f32[2][16][256] @20480 (32768B)
// ---------------------------------------------------------------------------
#define TCA   256
#define KTA   16
#define SMEM_K2A 53248
#define NTILES ((KTOT + KTA - 1) / KTA)   // 14

__global__ __launch_bounds__(256, 2) void k2a_gemm()
{
    extern __shared__ char smem[];
    const unsigned long long* s_coef2 = (const unsigned long long*)smem; // [2][16][8][10]
    const float* s_dirs = (const float*)(smem + 20480);                  // [2][16][256]
    unsigned smem_base = smem_u32(smem);

    int tid = threadIdx.x;
    int cbase = blockIdx.x * TCA;
    int bbase = blockIdx.y * 64;

    int lane = tid & 31;
    int wid  = tid >> 5;
    int g    = lane >> 2;               // batch group (8 batches)
    int cg2  = lane & 3;                // col group within warp slice
    int bq   = g * 8;                   // first batch of group
    int c0   = wid * 32 + cg2 * 8;      // first col of thread tile

#define STAGE(T, BUF)                                                          \
    {                                                                          \
        int kt_ = (T) * KTA;                                                   \
        int kmax_ = min(KTA, KTOT - kt_);                                      \
        for (int i = tid; i < kmax_ * 32; i += 256) {                          \
            int r = i >> 5, cc = i & 31;                                       \
            int gg = cc >> 2;                                                  \
            unsigned dst = smem_base + (BUF) * 10240 + r * 640 + cc * 16 + gg * 16; \
            const char* src = (const char*)&g_coefT2[(kt_ + r) * NBATCH + bbase] + cc * 16; \
            CP_ASYNC16(dst, src);                                              \
        }                                                                      \
        for (int i = tid; i < kmax_ * 64; i += 256) {                          \
            int r = i >> 6, ci = i & 63;                                       \
            unsigned dst = smem_base + 20480 + (BUF) * 16384 + r * 1024 + ci * 16;\
            const float* src = g_dirs + (size_t)(kt_ + r) * V3P + cbase + ci * 4; \
            CP_ASYNC16(dst, src);                                              \
        }                                                                      \
        CP_COMMIT();                                                           \
    }

    unsigned long long acc[8][4];
    #pragma unroll
    for (int i = 0; i < 8; i++)
        #pragma unroll
        for (int p = 0; p < 4; p++) acc[i][p] = 0ull;

#define GEMM_STEP(BUF, KK)                                                     \
    {                                                                          \
        const unsigned long long* cf = s_coef2 + (BUF) * 1280 + (KK) * 80 + g * 10; \
        ulonglong2 q0 = *(const ulonglong2*)(cf + 0);                          \
        ulonglong2 q1 = *(const ulonglong2*)(cf + 2);                          \
        ulonglong2 q2 = *(const ulonglong2*)(cf + 4);                          \
        ulonglong2 q3 = *(const ulonglong2*)(cf + 6);                          \
        const float* dr = s_dirs + (BUF) * 4096 + (KK) * 256 + c0;             \
        ulonglong2 d01 = *(const ulonglong2*)(dr);                             \
        ulonglong2 d23 = *(const ulonglong2*)(dr + 4);                         \
        FFMA2(acc[0][0], q0.x, d01.x); FFMA2(acc[0][1], q0.x, d01.y);          \
        FFMA2(acc[0][2], q0.x, d23.x); FFMA2(acc[0][3], q0.x, d23.y);          \
        FFMA2(acc[1][0], q0.y, d01.x); FFMA2(acc[1][1], q0.y, d01.y);          \
        FFMA2(acc[1][2], q0.y, d23.x); FFMA2(acc[1][3], q0.y, d23.y);          \
        FFMA2(acc[2][0], q1.x, d01.x); FFMA2(acc[2][1], q1.x, d01.y);          \
        FFMA2(acc[2][2], q1.x, d23.x); FFMA2(acc[2][3], q1.x, d23.y);          \
        FFMA2(acc[3][0], q1.y, d01.x); FFMA2(acc[3][1], q1.y, d01.y);          \
        FFMA2(acc[3][2], q1.y, d23.x); FFMA2(acc[3][3], q1.y, d23.y);          \
        FFMA2(acc[4][0], q2.x, d01.x); FFMA2(acc[4][1], q2.x, d01.y);          \
        FFMA2(acc[4][2], q2.x, d23.x); FFMA2(acc[4][3], q2.x, d23.y);          \
        FFMA2(acc[5][0], q2.y, d01.x); FFMA2(acc[5][1], q2.y, d01.y);          \
        FFMA2(acc[5][2], q2.y, d23.x); FFMA2(acc[5][3], q2.y, d23.y);          \
        FFMA2(acc[6][0], q3.x, d01.x); FFMA2(acc[6][1], q3.x, d01.y);          \
        FFMA2(acc[6][2], q3.x, d23.x); FFMA2(acc[6][3], q3.x, d23.y);          \
        FFMA2(acc[7][0], q3.y, d01.x); FFMA2(acc[7][1], q3.y, d01.y);          \
        FFMA2(acc[7][2], q3.y, d23.x); FFMA2(acc[7][3], q3.y, d23.y);          \
    }

    STAGE(0, 0)
    for (int t = 0; t < NTILES; t++) {
        int buf = t & 1;
        if (t + 1 < NTILES) {
            STAGE(t + 1, buf ^ 1)
            CP_WAIT(1);
        } else {
            CP_WAIT(0);
        }
        __syncthreads();
        int kmax = min(KTA, KTOT - t * KTA);
        if (kmax == KTA) {
            if (buf == 0) {
                #pragma unroll
                for (int kk = 0; kk < KTA; kk++) GEMM_STEP(0, kk)
            } else {
                #pragma unroll
                for (int kk = 0; kk < KTA; kk++) GEMM_STEP(1, kk)
            }
        } else {
            for (int kk = 0; kk < kmax; kk++) GEMM_STEP(buf, kk)
        }
        __syncthreads();
    }
#undef GEMM_STEP
#undef STAGE

    #pragma unroll
    for (int bi = 0; bi < 8; bi++) {
        size_t row = (size_t)(bbase + bq + bi) * V3;
        #pragma unroll
        for (int p = 0; p < 4; p++) {
            int col = cbase + c0 + p * 2;
            if (col < V3)
                *(unsigned long long*)&g_vposed[row + col] = acc[bi][p];
        }
    }
}

// ---------------------------------------------------------------------------
// K2b: LBS skinning. Block = 16 batches x 128 verts, 256 threads.
//   __launch_bounds__(256,3): cap regs at 85 -> 3 blocks/SM (was reg-limited
//   to 2 at regs=90; latency-bound kernel, +50% warps for hiding).
//   Dynamic smem (49792 B): s_A2 ull[16][290] @0, s_WT f32[24][132] @37120.
// ---------------------------------------------------------------------------
#define SMEM_K2B 49792

__global__ __launch_bounds__(256, 3) void k2b_lbs(
    float* __restrict__ out_verts)        // [B, V, 3]
{
    extern __shared__ char smemb[];
    unsigned long long* s_A2 = (unsigned long long*)smemb;   // [16][290]
    float* s_WT = (float*)(smemb + 37120);                   // [24][132]

    int tid = threadIdx.x;
    int vbase = blockIdx.x * 128;
    int bbase = blockIdx.y * 16;

    for (int i = tid; i < 16 * 288; i += 256) {
        int b = i / 288, j = i - b * 288;
        float v = g_A[(size_t)(bbase + b) * 288 + j];
        unsigned long long dv; PACK2(dv, v);
        s_A2[b * 290 + j] = dv;
    }
    for (int i = tid; i < 24 * 32; i += 256) {
        int j = i >> 5, q = i & 31;
        float4 w = *(const float4*)&g_lwT[j * NVL + vbase + q * 4];
        *(float4*)&s_WT[j * 132 + q * 4] = w;
    }
    __syncthreads();

    int bg = tid >> 4;        // 0..15 batch
    int vg = tid & 15;        // vertex group
    size_t brow = (size_t)(bbase + bg) * V3;

    #pragma unroll
    for (int pass = 0; pass < 2; pass++) {
        int v0 = vg * 4 + pass * 64;

        unsigned long long T[24];
        #pragma unroll
        for (int i = 0; i < 24; i++) T[i] = 0ull;

        #pragma unroll 4
        for (int j = 0; j < NJ; j++) {
            ulonglong2 W = *(const ulonglong2*)&s_WT[j * 132 + v0];
            const unsigned long long* Ab = &s_A2[bg * 290 + j * 12];
            ulonglong2 a0 = *(const ulonglong2*)(Ab + 0);
            ulonglong2 a1 = *(const ulonglong2*)(Ab + 2);
            ulonglong2 a2 = *(const ulonglong2*)(Ab + 4);
            ulonglong2 a3 = *(const ulonglong2*)(Ab + 6);
            ulonglong2 a4 = *(const ulonglong2*)(Ab + 8);
            ulonglong2 a5 = *(const ulonglong2*)(Ab + 10);
            FFMA2(T[0],  W.x, a0.x); FFMA2(T[1],  W.x, a0.y);
            FFMA2(T[2],  W.x, a1.x); FFMA2(T[3],  W.x, a1.y);
            FFMA2(T[4],  W.x, a2.x); FFMA2(T[5],  W.x, a2.y);
            FFMA2(T[6],  W.x, a3.x); FFMA2(T[7],  W.x, a3.y);
            FFMA2(T[8],  W.x, a4.x); FFMA2(T[9],  W.x, a4.y);
            FFMA2(T[10], W.x, a5.x); FFMA2(T[11], W.x, a5.y);
            FFMA2(T[12], W.y, a0.x); FFMA2(T[13], W.y, a0.y);
            FFMA2(T[14], W.y, a1.x); FFMA2(T[15], W.y, a1.y);
            FFMA2(T[16], W.y, a2.x); FFMA2(T[17], W.y, a2.y);
            FFMA2(T[18], W.y, a3.x); FFMA2(T[19], W.y, a3.y);
            FFMA2(T[20], W.y, a4.x); FFMA2(T[21], W.y, a4.y);
            FFMA2(T[22], W.y, a5.x); FFMA2(T[23], W.y, a5.y);
        }

        #pragma unroll
        for (int vp = 0; vp < 2; vp++) {
            float flo[12], fhi[12];
            #pragma unroll
            for (int c = 0; c < 12; c++) UNPACK2(flo[c], fhi[c], T[vp * 12 + c]);
            {
                int gv = vbase + v0 + vp * 2;
                if (gv < NV) {
                    const float* pp = g_vposed + brow + gv * 3;
                    float x = pp[0], y = pp[1], z = pp[2];
                    float* oo = out_verts + brow + gv * 3;
                    oo[0] = fmaf(flo[0], x, fmaf(flo[1], y, fmaf(flo[2],  z, flo[3])));
                    oo[1] = fmaf(flo[4], x, fmaf(flo[5], y, fmaf(flo[6],  z, flo[7])));
                    oo[2] = fmaf(flo[8], x, fmaf(flo[9], y, fmaf(flo[10], z, flo[11])));
                }
            }
            {
                int gv = vbase + v0 + vp * 2 + 1;
                if (gv < NV) {
                    const float* pp = g_vposed + brow + gv * 3;
                    float x = pp[0], y = pp[1], z = pp[2];
                    float* oo = out_verts + brow + gv * 3;
                    oo[0] = fmaf(fhi[0], x, fmaf(fhi[1], y, fmaf(fhi[2],  z, fhi[3])));
                    oo[1] = fmaf(fhi[4], x, fmaf(fhi[5], y, fmaf(fhi[6],  z, fhi[7])));
                    oo[2] = fmaf(fhi[8], x, fmaf(fhi[9], y, fmaf(fhi[10], z, fhi[11])));
                }
            }
        }
    }
}

// ---------------------------------------------------------------------------
// K3: joints[b,k,c] = sum_v jrT[k][v] * verts[b,v,c]; 2 batches per block.
// ---------------------------------------------------------------------------
__global__ __launch_bounds__(256) void k3_joints(
    const float* __restrict__ verts,    // [B, V, 3]
    float* __restrict__ out_joints)     // [B, 19, 3]
{
    int b0 = blockIdx.x * 2, tid = threadIdx.x;
    const float* vb0 = verts + (size_t)b0 * V3;
    const float* vb1 = vb0 + V3;
    float acc0[NK * 3], acc1[NK * 3];
    #pragma unroll
    for (int i = 0; i < NK * 3; i++) { acc0[i] = 0.f; acc1[i] = 0.f; }

    const int NQ = (NV + 3) / 4;
    for (int q = tid; q < NQ; q += 256) {
        int v0 = q * 4;
        const float* p0 = vb0 + v0 * 3;
        const float* p1 = vb1 + v0 * 3;
        float2 a0 = *(const float2*)(p0 + 0), a1 = *(const float2*)(p0 + 2);
        float2 a2 = *(const float2*)(p0 + 4), a3 = *(const float2*)(p0 + 6);
        float2 a4 = *(const float2*)(p0 + 8), a5 = *(const float2*)(p0 + 10);
        float2 c0 = *(const float2*)(p1 + 0), c1 = *(const float2*)(p1 + 2);
        float2 c2 = *(const float2*)(p1 + 4), c3 = *(const float2*)(p1 + 6);
        float2 c4 = *(const float2*)(p1 + 8), c5 = *(const float2*)(p1 + 10);
        #pragma unroll
        for (int k = 0; k < NK; k++) {
            float4 w = *(const float4*)&g_jrT[k * NVP + v0];
            acc0[k * 3 + 0] += w.x * a0.x + w.y * a1.y + w.z * a3.x + w.w * a4.y;
            acc0[k * 3 + 1] += w.x * a0.y + w.y * a2.x + w.z * a3.y + w.w * a5.x;
            acc0[k * 3 + 2] += w.x * a1.x + w.y * a2.y + w.z * a4.x + w.w * a5.y;
            acc1[k * 3 + 0] += w.x * c0.x + w.y * c1.y + w.z * c3.x + w.w * c4.y;
            acc1[k * 3 + 1] += w.x * c0.y + w.y * c2.x + w.z * c3.y + w.w * c5.x;
            acc1[k * 3 + 2] += w.x * c1.x + w.y * c2.y + w.z * c4.x + w.w * c5.y;
        }
    }

    __shared__ float s_part[8][2 * 58];
    int lane = tid & 31, wp = tid >> 5;
    #pragma unroll
    for (int i = 0; i < NK * 3; i++) {
        float v0 = acc0[i], v1 = acc1[i];
        #pragma unroll
        for (int off = 16; off; off >>= 1) {
            v0 += __shfl_down_sync(0xffffffffu, v0, off);
            v1 += __shfl_down_sync(0xffffffffu, v1, off);
        }
        if (lane == 0) { s_part[wp][i] = v0; s_part[wp][58 + i] = v1; }
    }
    __syncthreads();
    if (tid < 2 * NK * 3) {
        int h = tid / (NK * 3), i = tid - h * (NK * 3);
        float s = 0.f;
        #pragma unroll
        for (int w = 0; w < 8; w++) s += s_part[w][h * 58 + i];
        out_joints[(size_t)(b0 + h) * (NK * 3) + i] = s;
    }
}

// ---------------------------------------------------------------------------
extern "C" void kernel_launch(void* const* d_in, const int* in_sizes, int n_in,
                              void* d_out, int out_size) {
    const float* inputs    = (const float*)d_in[0];  // [B, 82]
    const float* v_tmpl    = (const float*)d_in[1];  // [V, 3]
    const float* shapedirs = (const float*)d_in[2];  // [10, V3]
    const float* jreg      = (const float*)d_in[3];  // [V, 24]
    const float* posedirs  = (const float*)d_in[4];  // [207, V3]
    const float* lbsw      = (const float*)d_in[5];  // [V, 24]
    const float* jntreg    = (const float*)d_in[6];  // [V, 19]

    float* out        = (float*)d_out;
    float* out_verts  = out;                                   // B*V*3
    float* out_joints = out + (size_t)NBATCH * NV * 3;         // B*19*3
    float* out_Rs     = out_joints + (size_t)NBATCH * NK * 3;  // B*24*9

    cudaFuncSetAttribute(k2a_gemm, cudaFuncAttributeMaxDynamicSharedMemorySize, SMEM_K2A);
    cudaFuncSetAttribute(k2b_lbs, cudaFuncAttributeMaxDynamicSharedMemorySize, SMEM_K2B);

    prep<<<PREP_DIRS, 256>>>(jreg, shapedirs, v_tmpl, posedirs, jntreg, lbsw);
    k1_batch<<<NBATCH, 64>>>(inputs, out_Rs);
    k2a_gemm<<<dim3(V3P / TCA, NBATCH / 64), 256, SMEM_K2A>>>();
    k2b_lbs<<<dim3((NV + 127) / 128, NBATCH / 16), 256, SMEM_K2B>>>(out_verts);
    k3_joints<<<NBATCH / 2, 256>>>(out_verts, out_joints);
}